// round 1
// baseline (speedup 1.0000x reference)
#include <cuda_runtime.h>
#include <math.h>

#define C_CLUST 10
#define D_IN    1024
#define D_H     512
#define D_ATT   256
#define N_CLS   4
#define N_MAX   10000

// ---------------- scratch (static device globals; no allocation) ----------------
__device__ int   g_is64;
__device__ int   g_count[C_CLUST];
__device__ int   g_off[C_CLUST];
__device__ int   g_cursor[C_CLUST];
__device__ int   g_idx[N_MAX];
__device__ float g_H1[(size_t)N_MAX * D_H];     // 20 MB
__device__ float g_pool[C_CLUST * D_H];          // per-cluster pooled SUM of h2
__device__ float g_hbuf[C_CLUST * D_H];          // h = relu(pooled@Wfc+bfc)
__device__ float g_Araw[C_CLUST];

__device__ __forceinline__ int get_cid(const void* cid, int n, int is64) {
    if (is64) return (int)((const long long*)cid)[n];
    return ((const int*)cid)[n];
}

// ---------------- pass 0: dtype detect + zero scratch ----------------
__global__ void k_init(const void* __restrict__ cid, int n) {
    int t = threadIdx.x;
    if (t == 0) {
        // int64 little-endian => odd int32 words are 0 (cluster ids in [0,10))
        const int* p = (const int*)cid;
        int allz = 1;
        for (int i = 1; i < 32; i += 2) if (p[i] != 0) { allz = 0; break; }
        g_is64 = allz;
    }
    if (t < C_CLUST) g_count[t] = 0;
    for (int i = t; i < C_CLUST * D_H; i += blockDim.x) g_pool[i] = 0.f;
}

// ---------------- pass 0b: histogram ----------------
__global__ void k_count(const void* __restrict__ cid, int n) {
    __shared__ int s[C_CLUST];
    int t = threadIdx.x;
    if (t < C_CLUST) s[t] = 0;
    __syncthreads();
    int i = blockIdx.x * blockDim.x + t;
    int is64 = g_is64;
    if (i < n) atomicAdd(&s[get_cid(cid, i, is64)], 1);
    __syncthreads();
    if (t < C_CLUST && s[t]) atomicAdd(&g_count[t], s[t]);
}

__global__ void k_offsets() {
    if (threadIdx.x == 0) {
        int o = 0;
        for (int c = 0; c < C_CLUST; c++) { g_off[c] = o; o += g_count[c]; g_cursor[c] = 0; }
    }
}

// ---------------- pass 0c: scatter (smem-aggregated) ----------------
__global__ void k_scatter(const void* __restrict__ cid, int n) {
    __shared__ int s_cnt[C_CLUST], s_base[C_CLUST];
    int t = threadIdx.x;
    if (t < C_CLUST) s_cnt[t] = 0;
    __syncthreads();
    int i = blockIdx.x * blockDim.x + t;
    int is64 = g_is64;
    int c = 0, lp = 0, valid = (i < n);
    if (valid) { c = get_cid(cid, i, is64); lp = atomicAdd(&s_cnt[c], 1); }
    __syncthreads();
    if (t < C_CLUST && s_cnt[t]) s_base[t] = atomicAdd(&g_cursor[t], s_cnt[t]);
    __syncthreads();
    if (valid) g_idx[g_off[c] + s_base[c] + lp] = i;
}

// ---------------- grouped GEMM: 128x128 tile, BK=8, 8x8 micro-tile ----------------
// GATHER: A rows come from x via g_idx; else A = g_H1 (contiguous segments).
// POOL:   fuse relu + column-sum + atomicAdd into g_pool (no H2 store);
//         else store relu result into g_H1.
template <bool GATHER, bool POOL>
__global__ void __launch_bounds__(256, 2)
k_gemm(const float* __restrict__ Aglob, const float* __restrict__ Wglob,
       const float* __restrict__ bias, int K) {
    int cid = blockIdx.z;
    int M = g_count[cid];
    int m0 = blockIdx.x * 128;
    if (m0 >= M) return;
    int n0 = blockIdx.y * 128;
    int seg = g_off[cid];
    const float* Wc_ = Wglob + (size_t)cid * K * D_H;

    __shared__ float As[8][128];
    __shared__ float Bs[8][128];

    int tid = threadIdx.x;
    int tx = tid & 15;        // 0..15 -> col group
    int ty = tid >> 4;        // 0..15 -> row group

    float acc[8][8];
#pragma unroll
    for (int i = 0; i < 8; i++)
#pragma unroll
        for (int j = 0; j < 8; j++) acc[i][j] = 0.f;

    // A tile load mapping: 128 rows x 8 k, each thread one float4
    int a_row = tid >> 1;
    int a_seg = (tid & 1) * 4;
    int gr = m0 + a_row;
    bool a_valid = gr < M;
    const float* Arow;
    if (GATHER) {
        int r = a_valid ? g_idx[seg + gr] : g_idx[seg];
        Arow = Aglob + (size_t)r * K;            // x rows, lda = K = 1024
    } else {
        int r = a_valid ? (seg + gr) : seg;
        Arow = g_H1 + (size_t)r * D_H;            // H1 rows, lda = 512 = K
    }
    // B tile load mapping: 8 k-rows x 128 cols, each thread one float4
    int b_row = tid >> 5;
    int b_col = (tid & 31) * 4;

    for (int k0 = 0; k0 < K; k0 += 8) {
        float4 av = a_valid ? *(const float4*)(Arow + k0 + a_seg)
                            : make_float4(0.f, 0.f, 0.f, 0.f);
        float4 bv = *(const float4*)(Wc_ + (size_t)(k0 + b_row) * D_H + n0 + b_col);
        __syncthreads();
        As[a_seg + 0][a_row] = av.x;
        As[a_seg + 1][a_row] = av.y;
        As[a_seg + 2][a_row] = av.z;
        As[a_seg + 3][a_row] = av.w;
        *(float4*)&Bs[b_row][b_col] = bv;
        __syncthreads();
#pragma unroll
        for (int kk = 0; kk < 8; kk++) {
            float a[8], b[8];
            *(float4*)(a)     = *(const float4*)&As[kk][ty * 8];
            *(float4*)(a + 4) = *(const float4*)&As[kk][ty * 8 + 4];
            *(float4*)(b)     = *(const float4*)&Bs[kk][tx * 8];
            *(float4*)(b + 4) = *(const float4*)&Bs[kk][tx * 8 + 4];
#pragma unroll
            for (int i = 0; i < 8; i++)
#pragma unroll
                for (int j = 0; j < 8; j++) acc[i][j] += a[i] * b[j];
        }
    }

    float bcol[8];
#pragma unroll
    for (int j = 0; j < 8; j++) bcol[j] = bias[cid * D_H + n0 + tx * 8 + j];

    if (!POOL) {
#pragma unroll
        for (int i = 0; i < 8; i++) {
            int r = m0 + ty * 8 + i;
            if (r < M) {
                float* o = &g_H1[(size_t)(seg + r) * D_H + n0 + tx * 8];
                float4 v;
                v.x = fmaxf(acc[i][0] + bcol[0], 0.f);
                v.y = fmaxf(acc[i][1] + bcol[1], 0.f);
                v.z = fmaxf(acc[i][2] + bcol[2], 0.f);
                v.w = fmaxf(acc[i][3] + bcol[3], 0.f);
                *(float4*)o = v;
                v.x = fmaxf(acc[i][4] + bcol[4], 0.f);
                v.y = fmaxf(acc[i][5] + bcol[5], 0.f);
                v.z = fmaxf(acc[i][6] + bcol[6], 0.f);
                v.w = fmaxf(acc[i][7] + bcol[7], 0.f);
                *(float4*)(o + 4) = v;
            }
        }
    } else {
        __shared__ float s_col[128];
        __syncthreads();            // main-loop smem reads done before reuse pattern below
        if (tid < 128) s_col[tid] = 0.f;
        __syncthreads();
        float part[8];
#pragma unroll
        for (int j = 0; j < 8; j++) part[j] = 0.f;
#pragma unroll
        for (int i = 0; i < 8; i++) {
            int r = m0 + ty * 8 + i;
            if (r < M) {
#pragma unroll
                for (int j = 0; j < 8; j++)
                    part[j] += fmaxf(acc[i][j] + bcol[j], 0.f);
            }
        }
#pragma unroll
        for (int j = 0; j < 8; j++) atomicAdd(&s_col[tx * 8 + j], part[j]);
        __syncthreads();
        if (tid < 128) atomicAdd(&g_pool[cid * D_H + n0 + tid], s_col[tid]);
    }
}

// ---------------- epilogue: h = relu(pooled @ Wfc + bfc), pooled = sum/count ----------------
__global__ void k_fc(const float* __restrict__ Wfc, const float* __restrict__ bfc) {
    int o = blockIdx.x * blockDim.x + threadIdx.x;
    if (o >= C_CLUST * D_H) return;
    int c = o >> 9;
    int j = o & 511;
    float inv = 1.f / (float)max(g_count[c], 1);
    const float* p = &g_pool[c * D_H];
    float s = 0.f;
#pragma unroll 8
    for (int k = 0; k < D_H; k++) s += p[k] * Wfc[k * D_H + j];
    g_hbuf[o] = fmaxf(s * inv + bfc[j], 0.f);
}

// ---------------- gated attention scores: A_raw[c] ----------------
__global__ void k_att(const float* __restrict__ Wa, const float* __restrict__ ba,
                      const float* __restrict__ Wb, const float* __restrict__ bb,
                      const float* __restrict__ Wc_, const float* __restrict__ bc_) {
    int c = blockIdx.x;
    int t = threadIdx.x;    // 256
    __shared__ float sh[D_H];
    for (int i = t; i < D_H; i += 256) sh[i] = g_hbuf[c * D_H + i];
    __syncthreads();
    float sa = 0.f, sb = 0.f;
#pragma unroll 4
    for (int k = 0; k < D_H; k++) {
        float hv = sh[k];
        sa += hv * Wa[k * D_ATT + t];
        sb += hv * Wb[k * D_ATT + t];
    }
    float gate = tanhf(sa + ba[t]) * (1.f / (1.f + expf(-(sb + bb[t]))));
    __shared__ float red[256];
    red[t] = gate * Wc_[t];
    __syncthreads();
    for (int s = 128; s > 0; s >>= 1) {
        if (t < s) red[t] += red[t + s];
        __syncthreads();
    }
    if (t == 0) g_Araw[c] = red[0] + bc_[0];
}

// ---------------- final: softmax(A) -> h_path -> rho -> classifier -> outputs ----------------
__global__ void k_final(const float* __restrict__ Wr, const float* __restrict__ br,
                        const float* __restrict__ Wcls, const float* __restrict__ bcls,
                        float* __restrict__ out, int out_size) {
    __shared__ float A[C_CLUST];
    __shared__ float hp[D_H];
    __shared__ float hr[D_ATT];
    __shared__ float lg[N_CLS];
    int t = threadIdx.x;    // 512
    if (t == 0) {
        float m = -1e30f;
        for (int c = 0; c < C_CLUST; c++) m = fmaxf(m, g_Araw[c]);
        float s = 0.f;
        for (int c = 0; c < C_CLUST; c++) { A[c] = expf(g_Araw[c] - m); s += A[c]; }
        float inv = 1.f / s;
        for (int c = 0; c < C_CLUST; c++) A[c] *= inv;
    }
    __syncthreads();
    if (t < D_H) {
        float s = 0.f;
#pragma unroll
        for (int c = 0; c < C_CLUST; c++) s += A[c] * g_hbuf[c * D_H + t];
        hp[t] = s;
    }
    __syncthreads();
    if (t < D_ATT) {
        float s = 0.f;
#pragma unroll 4
        for (int k = 0; k < D_H; k++) s += hp[k] * Wr[k * D_ATT + t];
        hr[t] = fmaxf(s + br[t], 0.f);
    }
    __syncthreads();
    if (t < N_CLS) {
        float s = 0.f;
#pragma unroll 4
        for (int k = 0; k < D_ATT; k++) s += hr[k] * Wcls[k * N_CLS + t];
        lg[t] = s + bcls[t];
    }
    __syncthreads();
    if (t == 0) {
        float m = lg[0];
        int am = 0;
        for (int i = 1; i < N_CLS; i++) if (lg[i] > m) { m = lg[i]; am = i; }
        float e[N_CLS], s = 0.f;
        for (int i = 0; i < N_CLS; i++) { e[i] = expf(lg[i] - m); s += e[i]; }
        float vals[9];
        for (int i = 0; i < N_CLS; i++) vals[i] = lg[i];
        for (int i = 0; i < N_CLS; i++) vals[4 + i] = e[i] / s;
        vals[8] = (float)am;
        for (int i = 0; i < out_size; i++) out[i] = (i < 9) ? vals[i] : 0.f;
    }
}

// ---------------- launch ----------------
extern "C" void kernel_launch(void* const* d_in, const int* in_sizes, int n_in,
                              void* d_out, int out_size) {
    const float* x    = (const float*)d_in[0];
    const void*  cid  = d_in[1];
    const float* W1   = (const float*)d_in[2];
    const float* b1   = (const float*)d_in[3];
    const float* W2   = (const float*)d_in[4];
    const float* b2   = (const float*)d_in[5];
    const float* Wfc  = (const float*)d_in[6];
    const float* bfc  = (const float*)d_in[7];
    const float* Wa   = (const float*)d_in[8];
    const float* ba   = (const float*)d_in[9];
    const float* Wb   = (const float*)d_in[10];
    const float* bb   = (const float*)d_in[11];
    const float* Wc_  = (const float*)d_in[12];
    const float* bc_  = (const float*)d_in[13];
    const float* Wr   = (const float*)d_in[14];
    const float* br   = (const float*)d_in[15];
    const float* Wcls = (const float*)d_in[16];
    const float* bcls = (const float*)d_in[17];

    int n = in_sizes[0] / D_IN;

    k_init<<<1, 512>>>(cid, n);
    k_count<<<(n + 255) / 256, 256>>>(cid, n);
    k_offsets<<<1, 32>>>();
    k_scatter<<<(n + 255) / 256, 256>>>(cid, n);

    dim3 gg((n + 127) / 128, D_H / 128, C_CLUST);
    k_gemm<true, false><<<gg, 256>>>(x, W1, b1, D_IN);   // H1 = relu(x@W1+b1)
    k_gemm<false, true><<<gg, 256>>>(x, W2, b2, D_H);    // pooled += relu(H1@W2+b2)

    k_fc<<<(C_CLUST * D_H + 127) / 128, 128>>>(Wfc, bfc);
    k_att<<<C_CLUST, 256>>>(Wa, ba, Wb, bb, Wc_, bc_);
    k_final<<<1, 512>>>(Wr, br, Wcls, bcls, (float*)d_out, out_size);
}

// round 2
// speedup vs baseline: 1.9153x; 1.9153x over previous
#include <cuda_runtime.h>
#include <math.h>
#include <stdint.h>

#define C_CLUST 10
#define D_IN    1024
#define D_H     512
#define D_ATT   256
#define N_CLS   4
#define N_MAX   10000

// ---------------- scratch (static device globals; no allocation) ----------------
__device__ int   g_is64;
__device__ int   g_count[C_CLUST];
__device__ int   g_off[C_CLUST];
__device__ int   g_cursor[C_CLUST];
__device__ int   g_idx[N_MAX];
__device__ float g_H1[(size_t)N_MAX * D_H];     // 20 MB
__device__ float g_pool[C_CLUST * D_H];          // per-cluster pooled SUM of h2
__device__ float g_hbuf[C_CLUST * D_H];          // h = relu(pooled@Wfc+bfc)
__device__ float g_Araw[C_CLUST];

__device__ __forceinline__ int get_cid(const void* cid, int n, int is64) {
    if (is64) return (int)((const long long*)cid)[n];
    return ((const int*)cid)[n];
}

__device__ __forceinline__ uint32_t f2tf32(float f) {
    uint32_t r;
    asm("cvt.rna.tf32.f32 %0, %1;" : "=r"(r) : "f"(f));
    return r;
}

__device__ __forceinline__ void mma_tf32(float c[4],
                                         uint32_t a0, uint32_t a1, uint32_t a2, uint32_t a3,
                                         uint32_t b0, uint32_t b1) {
    asm volatile(
        "mma.sync.aligned.m16n8k8.row.col.f32.tf32.tf32.f32 "
        "{%0,%1,%2,%3}, {%4,%5,%6,%7}, {%8,%9}, {%0,%1,%2,%3};\n"
        : "+f"(c[0]), "+f"(c[1]), "+f"(c[2]), "+f"(c[3])
        : "r"(a0), "r"(a1), "r"(a2), "r"(a3), "r"(b0), "r"(b1));
}

// ---------------- pass 0: dtype detect + zero scratch ----------------
__global__ void k_init(const void* __restrict__ cid, int n) {
    int t = threadIdx.x;
    if (t == 0) {
        const int* p = (const int*)cid;
        int allz = 1;
        for (int i = 1; i < 32; i += 2) if (p[i] != 0) { allz = 0; break; }
        g_is64 = allz;
    }
    if (t < C_CLUST) g_count[t] = 0;
    for (int i = t; i < C_CLUST * D_H; i += blockDim.x) g_pool[i] = 0.f;
}

// ---------------- pass 0b: histogram ----------------
__global__ void k_count(const void* __restrict__ cid, int n) {
    __shared__ int s[C_CLUST];
    int t = threadIdx.x;
    if (t < C_CLUST) s[t] = 0;
    __syncthreads();
    int i = blockIdx.x * blockDim.x + t;
    int is64 = g_is64;
    if (i < n) atomicAdd(&s[get_cid(cid, i, is64)], 1);
    __syncthreads();
    if (t < C_CLUST && s[t]) atomicAdd(&g_count[t], s[t]);
}

__global__ void k_offsets() {
    if (threadIdx.x == 0) {
        int o = 0;
        for (int c = 0; c < C_CLUST; c++) { g_off[c] = o; o += g_count[c]; g_cursor[c] = 0; }
    }
}

// ---------------- pass 0c: scatter (smem-aggregated) ----------------
__global__ void k_scatter(const void* __restrict__ cid, int n) {
    __shared__ int s_cnt[C_CLUST], s_base[C_CLUST];
    int t = threadIdx.x;
    if (t < C_CLUST) s_cnt[t] = 0;
    __syncthreads();
    int i = blockIdx.x * blockDim.x + t;
    int is64 = g_is64;
    int c = 0, lp = 0, valid = (i < n);
    if (valid) { c = get_cid(cid, i, is64); lp = atomicAdd(&s_cnt[c], 1); }
    __syncthreads();
    if (t < C_CLUST && s_cnt[t]) s_base[t] = atomicAdd(&g_cursor[t], s_cnt[t]);
    __syncthreads();
    if (valid) g_idx[g_off[c] + s_base[c] + lp] = i;
}

// ---------------- grouped GEMM via mma.sync tf32 ----------------
// CTA: 256 threads (8 warps), tile 128x128, K-chunk 32.
// Warp w: wm = w&1 (64-row half), wn = w>>2.. (w>>1, 32-col quarter).
// Each warp: 4x4 grid of m16n8k8 mma, accumulators in fp32 regs.
// GATHER: A rows gathered from x via g_idx (lda=K); else A = g_H1 segment (lda=D_H=K).
// POOL:   fused relu + column-sum + atomicAdd into g_pool (H2 never stored).
#define SA 36   // A smem row stride (floats): bank(g*36+tig) = 4g+tig -> conflict-free
#define SB 136  // B smem row stride (floats): bank(tig*136+g) = 8tig+g -> conflict-free

template <bool GATHER, bool POOL>
__global__ void __launch_bounds__(256, 2)
k_gemm_t(const float* __restrict__ Aglob, const float* __restrict__ Wglob,
         const float* __restrict__ bias, int K) {
    int cid = blockIdx.z;
    int M = g_count[cid];
    int m0 = blockIdx.x * 128;
    if (m0 >= M) return;
    int n0 = blockIdx.y * 128;
    int seg = g_off[cid];
    const float* Wc = Wglob + (size_t)cid * K * D_H;

    __shared__ uint32_t As[128 * SA];
    __shared__ uint32_t Bs[32 * SB];
    __shared__ float s_col[128];

    int tid = threadIdx.x;
    int lane = tid & 31;
    int w = tid >> 5;
    int wm = w & 1;          // 0..1
    int wn = w >> 1;         // 0..3
    int g = lane >> 2;       // 0..7
    int tig = lane & 3;      // 0..3

    float acc[4][4][4];
#pragma unroll
    for (int im = 0; im < 4; im++)
#pragma unroll
        for (int in = 0; in < 4; in++)
#pragma unroll
            for (int q = 0; q < 4; q++) acc[im][in][q] = 0.f;

    // gmem A mapping: row = tid>>1 (128 rows), cols = (tid&1)*16 .. +15
    int ar = tid >> 1;
    int ac = (tid & 1) * 16;
    bool a_valid = (m0 + ar) < M;
    const float* Arow;
    if (GATHER) {
        int r = a_valid ? g_idx[seg + m0 + ar] : 0;
        Arow = Aglob + (size_t)r * K;
    } else {
        int r = a_valid ? (seg + m0 + ar) : seg;
        Arow = g_H1 + (size_t)r * D_H;
    }
    // gmem B mapping: row = tid>>3 (32 rows), cols = (tid&7)*16 .. +15
    int br = tid >> 3;
    int bc = (tid & 7) * 16;
    const float* Brow0 = Wc + (size_t)br * D_H + n0 + bc;

    for (int k0 = 0; k0 < K; k0 += 32) {
        uint32_t av[16];
#pragma unroll
        for (int c4 = 0; c4 < 4; c4++) {
            float4 v = a_valid ? *(const float4*)(Arow + k0 + ac + c4 * 4)
                               : make_float4(0.f, 0.f, 0.f, 0.f);
            av[c4 * 4 + 0] = f2tf32(v.x);
            av[c4 * 4 + 1] = f2tf32(v.y);
            av[c4 * 4 + 2] = f2tf32(v.z);
            av[c4 * 4 + 3] = f2tf32(v.w);
        }
        uint32_t bvv[16];
#pragma unroll
        for (int c4 = 0; c4 < 4; c4++) {
            float4 v = *(const float4*)(Brow0 + (size_t)k0 * D_H + c4 * 4);
            bvv[c4 * 4 + 0] = f2tf32(v.x);
            bvv[c4 * 4 + 1] = f2tf32(v.y);
            bvv[c4 * 4 + 2] = f2tf32(v.z);
            bvv[c4 * 4 + 3] = f2tf32(v.w);
        }
        __syncthreads();
        {
            int abase = ar * SA + ac;
#pragma unroll
            for (int q = 0; q < 16; q++) As[abase + q] = av[q];
            int bbase = br * SB + bc;
#pragma unroll
            for (int q = 0; q < 16; q++) Bs[bbase + q] = bvv[q];
        }
        __syncthreads();

#pragma unroll
        for (int ks = 0; ks < 4; ks++) {
            uint32_t af[4][4];
#pragma unroll
            for (int im = 0; im < 4; im++) {
                int a0i = (wm * 64 + im * 16 + g) * SA + ks * 8 + tig;
                af[im][0] = As[a0i];
                af[im][1] = As[a0i + 8 * SA];
                af[im][2] = As[a0i + 4];
                af[im][3] = As[a0i + 8 * SA + 4];
            }
            uint32_t bf[4][2];
#pragma unroll
            for (int in = 0; in < 4; in++) {
                int b0i = (ks * 8 + tig) * SB + wn * 32 + in * 8 + g;
                bf[in][0] = Bs[b0i];
                bf[in][1] = Bs[b0i + 4 * SB];
            }
#pragma unroll
            for (int im = 0; im < 4; im++)
#pragma unroll
                for (int in = 0; in < 4; in++)
                    mma_tf32(acc[im][in], af[im][0], af[im][1], af[im][2], af[im][3],
                             bf[in][0], bf[in][1]);
        }
    }

    const float* bp = bias + cid * D_H + n0;

    if (!POOL) {
#pragma unroll
        for (int im = 0; im < 4; im++) {
            int rg = m0 + wm * 64 + im * 16 + g;
            int rg8 = rg + 8;
#pragma unroll
            for (int in = 0; in < 4; in++) {
                int col = wn * 32 + in * 8 + 2 * tig;
                float b0v = bp[col], b1v = bp[col + 1];
                if (rg < M) {
                    float2 v;
                    v.x = fmaxf(acc[im][in][0] + b0v, 0.f);
                    v.y = fmaxf(acc[im][in][1] + b1v, 0.f);
                    *(float2*)&g_H1[(size_t)(seg + rg) * D_H + n0 + col] = v;
                }
                if (rg8 < M) {
                    float2 v;
                    v.x = fmaxf(acc[im][in][2] + b0v, 0.f);
                    v.y = fmaxf(acc[im][in][3] + b1v, 0.f);
                    *(float2*)&g_H1[(size_t)(seg + rg8) * D_H + n0 + col] = v;
                }
            }
        }
    } else {
        if (tid < 128) s_col[tid] = 0.f;
        __syncthreads();
#pragma unroll
        for (int in = 0; in < 4; in++) {
            int col = wn * 32 + in * 8 + 2 * tig;
            float b0v = bp[col], b1v = bp[col + 1];
            float px = 0.f, py = 0.f;
#pragma unroll
            for (int im = 0; im < 4; im++) {
                int rg = m0 + wm * 64 + im * 16 + g;
                if (rg < M) {
                    px += fmaxf(acc[im][in][0] + b0v, 0.f);
                    py += fmaxf(acc[im][in][1] + b1v, 0.f);
                }
                if (rg + 8 < M) {
                    px += fmaxf(acc[im][in][2] + b0v, 0.f);
                    py += fmaxf(acc[im][in][3] + b1v, 0.f);
                }
            }
            atomicAdd(&s_col[col], px);
            atomicAdd(&s_col[col + 1], py);
        }
        __syncthreads();
        if (tid < 128) atomicAdd(&g_pool[cid * D_H + n0 + tid], s_col[tid]);
    }
}

// ---------------- epilogue: h = relu(pooled @ Wfc + bfc), pooled = sum/count ----------------
__global__ void k_fc(const float* __restrict__ Wfc, const float* __restrict__ bfc) {
    int o = blockIdx.x * blockDim.x + threadIdx.x;
    if (o >= C_CLUST * D_H) return;
    int c = o >> 9;
    int j = o & 511;
    float inv = 1.f / (float)max(g_count[c], 1);
    const float* p = &g_pool[c * D_H];
    float s = 0.f;
#pragma unroll 8
    for (int k = 0; k < D_H; k++) s += p[k] * Wfc[k * D_H + j];
    g_hbuf[o] = fmaxf(s * inv + bfc[j], 0.f);
}

// ---------------- gated attention scores: A_raw[c] ----------------
__global__ void k_att(const float* __restrict__ Wa, const float* __restrict__ ba,
                      const float* __restrict__ Wb, const float* __restrict__ bb,
                      const float* __restrict__ Wc_, const float* __restrict__ bc_) {
    int c = blockIdx.x;
    int t = threadIdx.x;    // 256
    __shared__ float sh[D_H];
    for (int i = t; i < D_H; i += 256) sh[i] = g_hbuf[c * D_H + i];
    __syncthreads();
    float sa = 0.f, sb = 0.f;
#pragma unroll 4
    for (int k = 0; k < D_H; k++) {
        float hv = sh[k];
        sa += hv * Wa[k * D_ATT + t];
        sb += hv * Wb[k * D_ATT + t];
    }
    float gate = tanhf(sa + ba[t]) * (1.f / (1.f + expf(-(sb + bb[t]))));
    __shared__ float red[256];
    red[t] = gate * Wc_[t];
    __syncthreads();
    for (int s = 128; s > 0; s >>= 1) {
        if (t < s) red[t] += red[t + s];
        __syncthreads();
    }
    if (t == 0) g_Araw[c] = red[0] + bc_[0];
}

// ---------------- final: softmax(A) -> h_path -> rho -> classifier -> outputs ----------------
__global__ void k_final(const float* __restrict__ Wr, const float* __restrict__ br,
                        const float* __restrict__ Wcls, const float* __restrict__ bcls,
                        float* __restrict__ out, int out_size) {
    __shared__ float A[C_CLUST];
    __shared__ float hp[D_H];
    __shared__ float hr[D_ATT];
    __shared__ float lg[N_CLS];
    int t = threadIdx.x;    // 512
    if (t == 0) {
        float m = -1e30f;
        for (int c = 0; c < C_CLUST; c++) m = fmaxf(m, g_Araw[c]);
        float s = 0.f;
        for (int c = 0; c < C_CLUST; c++) { A[c] = expf(g_Araw[c] - m); s += A[c]; }
        float inv = 1.f / s;
        for (int c = 0; c < C_CLUST; c++) A[c] *= inv;
    }
    __syncthreads();
    if (t < D_H) {
        float s = 0.f;
#pragma unroll
        for (int c = 0; c < C_CLUST; c++) s += A[c] * g_hbuf[c * D_H + t];
        hp[t] = s;
    }
    __syncthreads();
    if (t < D_ATT) {
        float s = 0.f;
#pragma unroll 4
        for (int k = 0; k < D_H; k++) s += hp[k] * Wr[k * D_ATT + t];
        hr[t] = fmaxf(s + br[t], 0.f);
    }
    __syncthreads();
    if (t < N_CLS) {
        float s = 0.f;
#pragma unroll 4
        for (int k = 0; k < D_ATT; k++) s += hr[k] * Wcls[k * N_CLS + t];
        lg[t] = s + bcls[t];
    }
    __syncthreads();
    if (t == 0) {
        float m = lg[0];
        int am = 0;
        for (int i = 1; i < N_CLS; i++) if (lg[i] > m) { m = lg[i]; am = i; }
        float e[N_CLS], s = 0.f;
        for (int i = 0; i < N_CLS; i++) { e[i] = expf(lg[i] - m); s += e[i]; }
        float vals[9];
        for (int i = 0; i < N_CLS; i++) vals[i] = lg[i];
        for (int i = 0; i < N_CLS; i++) vals[4 + i] = e[i] / s;
        vals[8] = (float)am;
        for (int i = 0; i < out_size; i++) out[i] = (i < 9) ? vals[i] : 0.f;
    }
}

// ---------------- launch ----------------
extern "C" void kernel_launch(void* const* d_in, const int* in_sizes, int n_in,
                              void* d_out, int out_size) {
    const float* x    = (const float*)d_in[0];
    const void*  cid  = d_in[1];
    const float* W1   = (const float*)d_in[2];
    const float* b1   = (const float*)d_in[3];
    const float* W2   = (const float*)d_in[4];
    const float* b2   = (const float*)d_in[5];
    const float* Wfc  = (const float*)d_in[6];
    const float* bfc  = (const float*)d_in[7];
    const float* Wa   = (const float*)d_in[8];
    const float* ba   = (const float*)d_in[9];
    const float* Wb   = (const float*)d_in[10];
    const float* bb   = (const float*)d_in[11];
    const float* Wc_  = (const float*)d_in[12];
    const float* bc_  = (const float*)d_in[13];
    const float* Wr   = (const float*)d_in[14];
    const float* br   = (const float*)d_in[15];
    const float* Wcls = (const float*)d_in[16];
    const float* bcls = (const float*)d_in[17];

    int n = in_sizes[0] / D_IN;

    k_init<<<1, 512>>>(cid, n);
    k_count<<<(n + 255) / 256, 256>>>(cid, n);
    k_offsets<<<1, 32>>>();
    k_scatter<<<(n + 255) / 256, 256>>>(cid, n);

    dim3 gg((n + 127) / 128, D_H / 128, C_CLUST);
    k_gemm_t<true, false><<<gg, 256>>>(x, W1, b1, D_IN);   // H1 = relu(x@W1+b1)
    k_gemm_t<false, true><<<gg, 256>>>(x, W2, b2, D_H);    // pooled += relu(H1@W2+b2)

    k_fc<<<(C_CLUST * D_H + 127) / 128, 128>>>(Wfc, bfc);
    k_att<<<C_CLUST, 256>>>(Wa, ba, Wb, bb, Wc_, bc_);
    k_final<<<1, 512>>>(Wr, br, Wcls, bcls, (float*)d_out, out_size);
}

// round 5
// speedup vs baseline: 1.9556x; 1.0210x over previous
#include <cuda_runtime.h>
#include <math.h>
#include <stdint.h>

#define C_CLUST 10
#define D_IN    1024
#define D_H     512
#define D_ATT   256
#define N_CLS   4
#define N_MAX   10000
#define NPAD    128

#define SA 36    // A smem row stride (floats), conflict-free fragment LDS
#define SB 136   // B smem row stride (floats)
#define KC 32
#define A_ST_BYTES (128 * SA * 4)          // 18432
#define B_ST_BYTES (32 * SB * 4)           // 17408
#define STAGE_BYTES (A_ST_BYTES + B_ST_BYTES)
#define SMEM_SZ (2 * STAGE_BYTES)          // 71680

// ---------------- scratch ----------------
__device__ int   g_is64;
__device__ int   g_count[C_CLUST];
__device__ int   g_off[C_CLUST];
__device__ int   g_cursor[C_CLUST];
__device__ int   g_idx[N_MAX];
__device__ float g_Xg[(size_t)(N_MAX + NPAD) * D_IN];   // gathered + tf32-rounded x
__device__ float g_H1[(size_t)(N_MAX + NPAD) * D_H];    // tf32-rounded H1
__device__ float g_W1r[(size_t)C_CLUST * D_IN * D_H];   // tf32-rounded W1 (same layout)
__device__ float g_W2r[(size_t)C_CLUST * D_H * D_H];
__device__ float g_pool[C_CLUST * D_H];
__device__ float g_hbuf[C_CLUST * D_H];
__device__ float g_Araw[C_CLUST];

__device__ __forceinline__ int get_cid(const void* cid, int n, int is64) {
    if (is64) return (int)((const long long*)cid)[n];
    return ((const int*)cid)[n];
}
__device__ __forceinline__ uint32_t f2tf32(float f) {
    uint32_t r; asm("cvt.rna.tf32.f32 %0, %1;" : "=r"(r) : "f"(f)); return r;
}
__device__ __forceinline__ uint32_t smem_u32(const void* p) {
    uint32_t a;
    asm("{ .reg .u64 t; cvta.to.shared.u64 t, %1; cvt.u32.u64 %0, t; }" : "=r"(a) : "l"(p));
    return a;
}
__device__ __forceinline__ void cp16(uint32_t smem, const void* gmem) {
    asm volatile("cp.async.cg.shared.global [%0], [%1], 16;" :: "r"(smem), "l"(gmem));
}
__device__ __forceinline__ void mma_tf32(float c[4],
                                         uint32_t a0, uint32_t a1, uint32_t a2, uint32_t a3,
                                         uint32_t b0, uint32_t b1) {
    asm volatile(
        "mma.sync.aligned.m16n8k8.row.col.f32.tf32.tf32.f32 "
        "{%0,%1,%2,%3}, {%4,%5,%6,%7}, {%8,%9}, {%0,%1,%2,%3};\n"
        : "+f"(c[0]), "+f"(c[1]), "+f"(c[2]), "+f"(c[3])
        : "r"(a0), "r"(a1), "r"(a2), "r"(a3), "r"(b0), "r"(b1));
}

// ---------------- prep: round W1/W2 to tf32, init counters, detect dtype ----------------
__global__ void k_prep(const float* __restrict__ W1, const float* __restrict__ W2,
                       const void* __restrict__ cid) {
    const size_t n1 = (size_t)C_CLUST * D_IN * D_H / 4;
    const size_t n2 = (size_t)C_CLUST * D_H * D_H / 4;
    size_t i = (size_t)blockIdx.x * blockDim.x + threadIdx.x;
    size_t stride = (size_t)gridDim.x * blockDim.x;
    for (size_t q = i; q < n1 + n2; q += stride) {
        const float4* src = (q < n1) ? (const float4*)W1 + q : (const float4*)W2 + (q - n1);
        uint4* dst = (q < n1) ? (uint4*)g_W1r + q : (uint4*)g_W2r + (q - n1);
        float4 v = *src;
        uint4 u;
        u.x = f2tf32(v.x); u.y = f2tf32(v.y); u.z = f2tf32(v.z); u.w = f2tf32(v.w);
        *dst = u;
    }
    if (blockIdx.x == 0) {
        int t = threadIdx.x;
        if (t == 0) {
            const int* p = (const int*)cid;
            int allz = 1;
            for (int k = 1; k < 32; k += 2) if (p[k] != 0) { allz = 0; break; }
            g_is64 = allz;
        }
        if (t < C_CLUST) g_count[t] = 0;
        for (int k = t; k < C_CLUST * D_H; k += blockDim.x) g_pool[k] = 0.f;
    }
}

__global__ void k_count(const void* __restrict__ cid, int n) {
    __shared__ int s[C_CLUST];
    int t = threadIdx.x;
    if (t < C_CLUST) s[t] = 0;
    __syncthreads();
    int i = blockIdx.x * blockDim.x + t;
    int is64 = g_is64;
    if (i < n) atomicAdd(&s[get_cid(cid, i, is64)], 1);
    __syncthreads();
    if (t < C_CLUST && s[t]) atomicAdd(&g_count[t], s[t]);
}

__global__ void k_offsets() {
    if (threadIdx.x == 0) {
        int o = 0;
        for (int c = 0; c < C_CLUST; c++) { g_off[c] = o; o += g_count[c]; g_cursor[c] = 0; }
    }
}

__global__ void k_scatter(const void* __restrict__ cid, int n) {
    __shared__ int s_cnt[C_CLUST], s_base[C_CLUST];
    int t = threadIdx.x;
    if (t < C_CLUST) s_cnt[t] = 0;
    __syncthreads();
    int i = blockIdx.x * blockDim.x + t;
    int is64 = g_is64;
    int c = 0, lp = 0, valid = (i < n);
    if (valid) { c = get_cid(cid, i, is64); lp = atomicAdd(&s_cnt[c], 1); }
    __syncthreads();
    if (t < C_CLUST && s_cnt[t]) s_base[t] = atomicAdd(&g_cursor[t], s_cnt[t]);
    __syncthreads();
    if (valid) g_idx[g_off[c] + s_base[c] + lp] = i;
}

// gather x rows into cluster order + tf32 round; 1 block per point, 256 thr -> 256 float4
__global__ void k_gather(const float* __restrict__ x, int n) {
    int p = blockIdx.x;
    if (p >= n) return;
    int row = g_idx[p];
    const float4* src = (const float4*)(x + (size_t)row * D_IN);
    uint4* dst = (uint4*)(g_Xg + (size_t)p * D_IN);
    int t = threadIdx.x;
    float4 v = src[t];
    uint4 u;
    u.x = f2tf32(v.x); u.y = f2tf32(v.y); u.z = f2tf32(v.z); u.w = f2tf32(v.w);
    dst[t] = u;
}

// ---------------- pipelined tf32 mma.sync grouped GEMM ----------------
// Tile 128x128, 8 warps, warp = 64x32 (4x4 m16n8k8). KC=32, cp.async double buffer.
// A rows contiguous (g_Xg or g_H1), pre-rounded. B = pre-rounded W, [c][k][n].
// POOL: fused relu + column-sum + atomics into g_pool (no H2 store).
template <bool POOL>
__global__ void __launch_bounds__(256, 2)
k_gemm(const float* __restrict__ Aglob, const float* __restrict__ Wglob,
       const float* __restrict__ bias, int K) {
    int cid = blockIdx.z;
    int M = g_count[cid];
    int m0 = blockIdx.x * 128;
    if (m0 >= M) return;
    int n0 = blockIdx.y * 128;
    int seg = g_off[cid];
    const float* Wc = Wglob + (size_t)cid * K * D_H;

    extern __shared__ char dsm[];
    __shared__ float s_col[128];
    uint32_t sbase = smem_u32(dsm);

    int tid = threadIdx.x;
    int lane = tid & 31;
    int w = tid >> 5;
    int wm = w & 1;
    int wn = w >> 1;
    int g = lane >> 2;
    int tig = lane & 3;

    float acc[4][4][4];
#pragma unroll
    for (int im = 0; im < 4; im++)
#pragma unroll
        for (int in = 0; in < 4; in++)
#pragma unroll
            for (int q = 0; q < 4; q++) acc[im][in][q] = 0.f;

    // cp.async mappings
    int ar = tid >> 1, ak = (tid & 1) * 16;               // A: row, k-offset
    int br = tid >> 3, bc = (tid & 7) * 16;               // B: k-row, col-offset
    const float* Arow = Aglob + (size_t)(seg + m0 + ar) * K + ak;   // FIX: + ak
    const float* Brow = Wc + (size_t)br * D_H + n0 + bc;

    uint32_t a_sm_off = (ar * SA + ak) * 4;
    uint32_t b_sm_off = A_ST_BYTES + (br * SB + bc) * 4;

    int nch = K / KC;

    // prologue: stage 0
    {
        uint32_t st = sbase;
#pragma unroll
        for (int q = 0; q < 4; q++) cp16(st + a_sm_off + q * 16, Arow + q * 4);
#pragma unroll
        for (int q = 0; q < 4; q++) cp16(st + b_sm_off + q * 16, Brow + q * 4);
        asm volatile("cp.async.commit_group;" ::: "memory");
    }

    for (int c = 0; c < nch; c++) {
        if (c + 1 < nch) {
            uint32_t st = sbase + ((c + 1) & 1) * STAGE_BYTES;
            const float* ap = Arow + (c + 1) * KC;
            const float* bp = Brow + (size_t)(c + 1) * KC * D_H;
#pragma unroll
            for (int q = 0; q < 4; q++) cp16(st + a_sm_off + q * 16, ap + q * 4);
#pragma unroll
            for (int q = 0; q < 4; q++) cp16(st + b_sm_off + q * 16, bp + q * 4);
            asm volatile("cp.async.commit_group;" ::: "memory");
            asm volatile("cp.async.wait_group 1;" ::: "memory");
        } else {
            asm volatile("cp.async.wait_group 0;" ::: "memory");
        }
        __syncthreads();

        const uint32_t* As = (const uint32_t*)(dsm + (c & 1) * STAGE_BYTES);
        const uint32_t* Bs = (const uint32_t*)(dsm + (c & 1) * STAGE_BYTES + A_ST_BYTES);
#pragma unroll
        for (int ks = 0; ks < 4; ks++) {
            uint32_t af[4][4];
#pragma unroll
            for (int im = 0; im < 4; im++) {
                int a0i = (wm * 64 + im * 16 + g) * SA + ks * 8 + tig;
                af[im][0] = As[a0i];
                af[im][1] = As[a0i + 8 * SA];
                af[im][2] = As[a0i + 4];
                af[im][3] = As[a0i + 8 * SA + 4];
            }
            uint32_t bf[4][2];
#pragma unroll
            for (int in = 0; in < 4; in++) {
                int b0i = (ks * 8 + tig) * SB + wn * 32 + in * 8 + g;
                bf[in][0] = Bs[b0i];
                bf[in][1] = Bs[b0i + 4 * SB];
            }
#pragma unroll
            for (int im = 0; im < 4; im++)
#pragma unroll
                for (int in = 0; in < 4; in++)
                    mma_tf32(acc[im][in], af[im][0], af[im][1], af[im][2], af[im][3],
                             bf[in][0], bf[in][1]);
        }
        __syncthreads();
    }

    const float* bp = bias + cid * D_H + n0;

    if (!POOL) {
#pragma unroll
        for (int im = 0; im < 4; im++) {
            int rg = m0 + wm * 64 + im * 16 + g;
            int rg8 = rg + 8;
#pragma unroll
            for (int in = 0; in < 4; in++) {
                int col = wn * 32 + in * 8 + 2 * tig;
                float b0v = bp[col], b1v = bp[col + 1];
                if (rg < M) {
                    uint2 v;
                    v.x = f2tf32(fmaxf(acc[im][in][0] + b0v, 0.f));
                    v.y = f2tf32(fmaxf(acc[im][in][1] + b1v, 0.f));
                    *(uint2*)&g_H1[(size_t)(seg + rg) * D_H + n0 + col] = v;
                }
                if (rg8 < M) {
                    uint2 v;
                    v.x = f2tf32(fmaxf(acc[im][in][2] + b0v, 0.f));
                    v.y = f2tf32(fmaxf(acc[im][in][3] + b1v, 0.f));
                    *(uint2*)&g_H1[(size_t)(seg + rg8) * D_H + n0 + col] = v;
                }
            }
        }
    } else {
        if (tid < 128) s_col[tid] = 0.f;
        __syncthreads();
#pragma unroll
        for (int in = 0; in < 4; in++) {
            int col = wn * 32 + in * 8 + 2 * tig;
            float b0v = bp[col], b1v = bp[col + 1];
            float px = 0.f, py = 0.f;
#pragma unroll
            for (int im = 0; im < 4; im++) {
                int rg = m0 + wm * 64 + im * 16 + g;
                if (rg < M) {
                    px += fmaxf(acc[im][in][0] + b0v, 0.f);
                    py += fmaxf(acc[im][in][1] + b1v, 0.f);
                }
                if (rg + 8 < M) {
                    px += fmaxf(acc[im][in][2] + b0v, 0.f);
                    py += fmaxf(acc[im][in][3] + b1v, 0.f);
                }
            }
            atomicAdd(&s_col[col], px);
            atomicAdd(&s_col[col + 1], py);
        }
        __syncthreads();
        if (tid < 128) atomicAdd(&g_pool[cid * D_H + n0 + tid], s_col[tid]);
    }
}

// ---------------- epilogue chain ----------------
__global__ void k_fc(const float* __restrict__ Wfc, const float* __restrict__ bfc) {
    int o = blockIdx.x * blockDim.x + threadIdx.x;
    if (o >= C_CLUST * D_H) return;
    int c = o >> 9;
    int j = o & 511;
    float inv = 1.f / (float)max(g_count[c], 1);
    const float* p = &g_pool[c * D_H];
    float s = 0.f;
#pragma unroll 8
    for (int k = 0; k < D_H; k++) s += p[k] * Wfc[k * D_H + j];
    g_hbuf[o] = fmaxf(s * inv + bfc[j], 0.f);
}

__global__ void k_att(const float* __restrict__ Wa, const float* __restrict__ ba,
                      const float* __restrict__ Wb, const float* __restrict__ bb,
                      const float* __restrict__ Wc_, const float* __restrict__ bc_) {
    int c = blockIdx.x;
    int t = threadIdx.x;
    __shared__ float sh[D_H];
    for (int i = t; i < D_H; i += 256) sh[i] = g_hbuf[c * D_H + i];
    __syncthreads();
    float sa = 0.f, sb = 0.f;
#pragma unroll 4
    for (int k = 0; k < D_H; k++) {
        float hv = sh[k];
        sa += hv * Wa[k * D_ATT + t];
        sb += hv * Wb[k * D_ATT + t];
    }
    float gate = tanhf(sa + ba[t]) * (1.f / (1.f + expf(-(sb + bb[t]))));
    __shared__ float red[256];
    red[t] = gate * Wc_[t];
    __syncthreads();
    for (int s = 128; s > 0; s >>= 1) {
        if (t < s) red[t] += red[t + s];
        __syncthreads();
    }
    if (t == 0) g_Araw[c] = red[0] + bc_[0];
}

__global__ void k_final(const float* __restrict__ Wr, const float* __restrict__ br,
                        const float* __restrict__ Wcls, const float* __restrict__ bcls,
                        float* __restrict__ out, int out_size) {
    __shared__ float A[C_CLUST];
    __shared__ float hp[D_H];
    __shared__ float hr[D_ATT];
    __shared__ float lg[N_CLS];
    int t = threadIdx.x;
    if (t == 0) {
        float m = -1e30f;
        for (int c = 0; c < C_CLUST; c++) m = fmaxf(m, g_Araw[c]);
        float s = 0.f;
        for (int c = 0; c < C_CLUST; c++) { A[c] = expf(g_Araw[c] - m); s += A[c]; }
        float inv = 1.f / s;
        for (int c = 0; c < C_CLUST; c++) A[c] *= inv;
    }
    __syncthreads();
    if (t < D_H) {
        float s = 0.f;
#pragma unroll
        for (int c = 0; c < C_CLUST; c++) s += A[c] * g_hbuf[c * D_H + t];
        hp[t] = s;
    }
    __syncthreads();
    if (t < D_ATT) {
        float s = 0.f;
#pragma unroll 4
        for (int k = 0; k < D_H; k++) s += hp[k] * Wr[k * D_ATT + t];
        hr[t] = fmaxf(s + br[t], 0.f);
    }
    __syncthreads();
    if (t < N_CLS) {
        float s = 0.f;
#pragma unroll 4
        for (int k = 0; k < D_ATT; k++) s += hr[k] * Wcls[k * N_CLS + t];
        lg[t] = s + bcls[t];
    }
    __syncthreads();
    if (t == 0) {
        float m = lg[0];
        int am = 0;
        for (int i = 1; i < N_CLS; i++) if (lg[i] > m) { m = lg[i]; am = i; }
        float e[N_CLS], s = 0.f;
        for (int i = 0; i < N_CLS; i++) { e[i] = expf(lg[i] - m); s += e[i]; }
        float vals[9];
        for (int i = 0; i < N_CLS; i++) vals[i] = lg[i];
        for (int i = 0; i < N_CLS; i++) vals[4 + i] = e[i] / s;
        vals[8] = (float)am;
        for (int i = 0; i < out_size; i++) out[i] = (i < 9) ? vals[i] : 0.f;
    }
}

// ---------------- launch ----------------
extern "C" void kernel_launch(void* const* d_in, const int* in_sizes, int n_in,
                              void* d_out, int out_size) {
    const float* x    = (const float*)d_in[0];
    const void*  cid  = d_in[1];
    const float* W1   = (const float*)d_in[2];
    const float* b1   = (const float*)d_in[3];
    const float* W2   = (const float*)d_in[4];
    const float* b2   = (const float*)d_in[5];
    const float* Wfc  = (const float*)d_in[6];
    const float* bfc  = (const float*)d_in[7];
    const float* Wa   = (const float*)d_in[8];
    const float* ba   = (const float*)d_in[9];
    const float* Wb   = (const float*)d_in[10];
    const float* bb   = (const float*)d_in[11];
    const float* Wc_  = (const float*)d_in[12];
    const float* bc_  = (const float*)d_in[13];
    const float* Wr   = (const float*)d_in[14];
    const float* br   = (const float*)d_in[15];
    const float* Wcls = (const float*)d_in[16];
    const float* bcls = (const float*)d_in[17];

    int n = in_sizes[0] / D_IN;

    static float* xg_p = nullptr;
    static float* h1_p = nullptr;
    static float* w1r_p = nullptr;
    static float* w2r_p = nullptr;
    if (!xg_p) {
        cudaGetSymbolAddress((void**)&xg_p, g_Xg);
        cudaGetSymbolAddress((void**)&h1_p, g_H1);
        cudaGetSymbolAddress((void**)&w1r_p, g_W1r);
        cudaGetSymbolAddress((void**)&w2r_p, g_W2r);
        cudaFuncSetAttribute(k_gemm<false>, cudaFuncAttributeMaxDynamicSharedMemorySize, SMEM_SZ);
        cudaFuncSetAttribute(k_gemm<true>, cudaFuncAttributeMaxDynamicSharedMemorySize, SMEM_SZ);
    }

    k_prep<<<4096, 256>>>(W1, W2, cid);                       // 1
    k_count<<<(n + 255) / 256, 256>>>(cid, n);                // 2
    k_offsets<<<1, 32>>>();                                   // 3
    k_scatter<<<(n + 255) / 256, 256>>>(cid, n);              // 4
    k_gather<<<n, 256>>>(x, n);                               // 5

    dim3 gg((n + 127) / 128, D_H / 128, C_CLUST);
    k_gemm<false><<<gg, 256, SMEM_SZ>>>(xg_p, w1r_p, b1, D_IN);  // 6  <- ncu -s5 lands here
    k_gemm<true><<<gg, 256, SMEM_SZ>>>(h1_p, w2r_p, b2, D_H);    // 7

    k_fc<<<(C_CLUST * D_H + 127) / 128, 128>>>(Wfc, bfc);
    k_att<<<C_CLUST, 256>>>(Wa, ba, Wb, bb, Wc_, bc_);
    k_final<<<1, 512>>>(Wr, br, Wcls, bcls, (float*)d_out, out_size);
}

// round 6
// speedup vs baseline: 2.4951x; 1.2759x over previous
#include <cuda_runtime.h>
#include <cuda_bf16.h>
#include <math.h>
#include <stdint.h>

#define C_CLUST 10
#define D_IN    1024
#define D_H     512
#define D_ATT   256
#define N_CLS   4
#define N_MAX   10000
#define NPAD    128

#define KC 64
#define SAH 72                              // smem row stride in bf16 elems (144 B)
#define ROWB 144                            // row stride bytes
#define A_BYTES (128 * ROWB)                // 18432
#define STAGE_BYTES (2 * A_BYTES)           // A + B tiles
#define SMEM_SZ (2 * STAGE_BYTES)           // 73728

// ---------------- scratch ----------------
__device__ int   g_is64;
__device__ int   g_count[C_CLUST];
__device__ int   g_off[C_CLUST];
__device__ int   g_cursor[C_CLUST];
__device__ int   g_idx[N_MAX];
__device__ __nv_bfloat16 g_Xg[(size_t)(N_MAX + NPAD) * D_IN];    // gathered bf16 x
__device__ __nv_bfloat16 g_H1[(size_t)(N_MAX + NPAD) * D_H];     // bf16 H1
__device__ __nv_bfloat16 g_W1t[(size_t)C_CLUST * D_H * D_IN];    // W1^T bf16 [c][n][k]
__device__ __nv_bfloat16 g_W2t[(size_t)C_CLUST * D_H * D_H];     // W2^T bf16
__device__ float g_pool[C_CLUST * D_H];
__device__ float g_hbuf[C_CLUST * D_H];
__device__ float g_Araw[C_CLUST];

__device__ __forceinline__ int get_cid(const void* cid, int n, int is64) {
    if (is64) return (int)((const long long*)cid)[n];
    return ((const int*)cid)[n];
}
__device__ __forceinline__ uint32_t smem_u32(const void* p) {
    uint32_t a;
    asm("{ .reg .u64 t; cvta.to.shared.u64 t, %1; cvt.u32.u64 %0, t; }" : "=r"(a) : "l"(p));
    return a;
}
__device__ __forceinline__ void cp16(uint32_t smem, const void* gmem) {
    asm volatile("cp.async.cg.shared.global [%0], [%1], 16;" :: "r"(smem), "l"(gmem));
}
__device__ __forceinline__ void ldsm4(uint32_t& r0, uint32_t& r1, uint32_t& r2, uint32_t& r3,
                                      uint32_t addr) {
    asm volatile("ldmatrix.sync.aligned.m8n8.x4.shared.b16 {%0,%1,%2,%3}, [%4];"
                 : "=r"(r0), "=r"(r1), "=r"(r2), "=r"(r3) : "r"(addr));
}
__device__ __forceinline__ void mma_bf16(float c[4], uint32_t a0, uint32_t a1, uint32_t a2,
                                         uint32_t a3, uint32_t b0, uint32_t b1) {
    asm volatile(
        "mma.sync.aligned.m16n8k16.row.col.f32.bf16.bf16.f32 "
        "{%0,%1,%2,%3}, {%4,%5,%6,%7}, {%8,%9}, {%0,%1,%2,%3};\n"
        : "+f"(c[0]), "+f"(c[1]), "+f"(c[2]), "+f"(c[3])
        : "r"(a0), "r"(a1), "r"(a2), "r"(a3), "r"(b0), "r"(b1));
}

// ---------------- pre-pass kernels ----------------
__global__ void k_init(const void* __restrict__ cid) {
    int t = threadIdx.x;
    if (t == 0) {
        const int* p = (const int*)cid;
        int allz = 1;
        for (int i = 1; i < 32; i += 2) if (p[i] != 0) { allz = 0; break; }
        g_is64 = allz;
    }
    if (t < C_CLUST) g_count[t] = 0;
    for (int i = t; i < C_CLUST * D_H; i += blockDim.x) g_pool[i] = 0.f;
}

__global__ void k_count(const void* __restrict__ cid, int n) {
    __shared__ int s[C_CLUST];
    int t = threadIdx.x;
    if (t < C_CLUST) s[t] = 0;
    __syncthreads();
    int i = blockIdx.x * blockDim.x + t;
    int is64 = g_is64;
    if (i < n) atomicAdd(&s[get_cid(cid, i, is64)], 1);
    __syncthreads();
    if (t < C_CLUST && s[t]) atomicAdd(&g_count[t], s[t]);
}

__global__ void k_offsets() {
    if (threadIdx.x == 0) {
        int o = 0;
        for (int c = 0; c < C_CLUST; c++) { g_off[c] = o; o += g_count[c]; g_cursor[c] = 0; }
    }
}

__global__ void k_scatter(const void* __restrict__ cid, int n) {
    __shared__ int s_cnt[C_CLUST], s_base[C_CLUST];
    int t = threadIdx.x;
    if (t < C_CLUST) s_cnt[t] = 0;
    __syncthreads();
    int i = blockIdx.x * blockDim.x + t;
    int is64 = g_is64;
    int c = 0, lp = 0, valid = (i < n);
    if (valid) { c = get_cid(cid, i, is64); lp = atomicAdd(&s_cnt[c], 1); }
    __syncthreads();
    if (t < C_CLUST && s_cnt[t]) s_base[t] = atomicAdd(&g_cursor[t], s_cnt[t]);
    __syncthreads();
    if (valid) g_idx[g_off[c] + s_base[c] + lp] = i;
}

// gather x rows into cluster order as bf16
__global__ void k_gather(const float* __restrict__ x, int n) {
    int p = blockIdx.x;
    if (p >= n) return;
    int row = g_idx[p];
    const float4* src = (const float4*)(x + (size_t)row * D_IN);
    uint2* dst = (uint2*)(g_Xg + (size_t)p * D_IN);
    int t = threadIdx.x;
    float4 v = src[t];
    __nv_bfloat162 lo = __floats2bfloat162_rn(v.x, v.y);
    __nv_bfloat162 hi = __floats2bfloat162_rn(v.z, v.w);
    uint2 u;
    u.x = *(uint32_t*)&lo;
    u.y = *(uint32_t*)&hi;
    dst[t] = u;
}

// W [c][R][C] fp32 -> Wt [c][C][R] bf16. blockDim (32,8).
__global__ void k_tr(const float* __restrict__ in, __nv_bfloat16* __restrict__ out,
                     int R, int C) {
    __shared__ float tl[32][33];
    int c = blockIdx.z;
    const float* src = in + (size_t)c * R * C;
    __nv_bfloat16* dst = out + (size_t)c * R * C;
    int r0 = blockIdx.y * 32, c0 = blockIdx.x * 32;
    int tx = threadIdx.x, ty = threadIdx.y;
#pragma unroll
    for (int i = 0; i < 32; i += 8)
        tl[ty + i][tx] = src[(size_t)(r0 + ty + i) * C + c0 + tx];
    __syncthreads();
#pragma unroll
    for (int i = 0; i < 32; i += 8)
        dst[(size_t)(c0 + ty + i) * R + r0 + tx] = __float2bfloat16_rn(tl[tx][ty + i]);
}

// ---------------- bf16 mma.sync grouped GEMM ----------------
// Tile 128x128, 8 warps (warp = 64x32 via 4x4 m16n8k16), KC=64, cp.async double buffer,
// ldmatrix.x4 fragment loads. A: [m][k] bf16 rows (g_Xg or g_H1). B: Wt [c][n][k] bf16.
// POOL: fused relu + column-sum + atomics into g_pool.
template <bool POOL>
__global__ void __launch_bounds__(256, 2)
k_gemm(const __nv_bfloat16* __restrict__ Aglob, const __nv_bfloat16* __restrict__ Wt,
       const float* __restrict__ bias, int K) {
    int cid = blockIdx.z;
    int M = g_count[cid];
    int m0 = blockIdx.x * 128;
    if (m0 >= M) return;
    int n0 = blockIdx.y * 128;
    int seg = g_off[cid];
    const __nv_bfloat16* Wc = Wt + (size_t)cid * D_H * K;

    extern __shared__ char dsm[];
    __shared__ float s_col[128];
    uint32_t sbase = smem_u32(dsm);

    int tid = threadIdx.x;
    int lane = tid & 31;
    int w = tid >> 5;
    int wm = w & 1;
    int wn = w >> 1;
    int g = lane >> 2;
    int tig = lane & 3;
    int l7 = lane & 7, l8 = (lane >> 3) & 1, l16 = lane >> 4;

    float acc[4][4][4];
#pragma unroll
    for (int im = 0; im < 4; im++)
#pragma unroll
        for (int in = 0; in < 4; in++)
#pragma unroll
            for (int q = 0; q < 4; q++) acc[im][in][q] = 0.f;

    // cp.async mappings: 2 threads/row, 4x 16B chunks each (KC=64 bf16 = 128 B/row)
    int ar = tid >> 1;
    int acs = (tid & 1) * 4;
    const __nv_bfloat16* Arow = Aglob + (size_t)(seg + m0 + ar) * K + acs * 8;
    const __nv_bfloat16* Brow = Wc + (size_t)(n0 + ar) * K + acs * 8;
    uint32_t a_sm = ar * ROWB + acs * 16;
    uint32_t b_sm = A_BYTES + a_sm;

    // ldmatrix per-lane fragment offsets
    uint32_t a_frag = (uint32_t)(wm * 64 + l7 + 8 * l8) * ROWB + 16 * l16;
    uint32_t b_frag = A_BYTES + (uint32_t)(wn * 32 + l7 + 8 * l8) * ROWB + 16 * l16;

    int nch = K / KC;
    {
        uint32_t st = sbase;
#pragma unroll
        for (int q = 0; q < 4; q++) cp16(st + a_sm + q * 16, Arow + q * 8);
#pragma unroll
        for (int q = 0; q < 4; q++) cp16(st + b_sm + q * 16, Brow + q * 8);
        asm volatile("cp.async.commit_group;" ::: "memory");
    }

    for (int c = 0; c < nch; c++) {
        if (c + 1 < nch) {
            uint32_t st = sbase + ((c + 1) & 1) * STAGE_BYTES;
            const __nv_bfloat16* ap = Arow + (c + 1) * KC;
            const __nv_bfloat16* bp = Brow + (c + 1) * KC;
#pragma unroll
            for (int q = 0; q < 4; q++) cp16(st + a_sm + q * 16, ap + q * 8);
#pragma unroll
            for (int q = 0; q < 4; q++) cp16(st + b_sm + q * 16, bp + q * 8);
            asm volatile("cp.async.commit_group;" ::: "memory");
            asm volatile("cp.async.wait_group 1;" ::: "memory");
        } else {
            asm volatile("cp.async.wait_group 0;" ::: "memory");
        }
        __syncthreads();

        uint32_t stb = sbase + (c & 1) * STAGE_BYTES;
#pragma unroll
        for (int ks = 0; ks < 4; ks++) {
            uint32_t koff = ks * 32;
            uint32_t bfr[2][4];
#pragma unroll
            for (int p = 0; p < 2; p++)
                ldsm4(bfr[p][0], bfr[p][1], bfr[p][2], bfr[p][3],
                      stb + b_frag + p * (16 * ROWB) + koff);
            uint32_t afr[4][4];
#pragma unroll
            for (int im = 0; im < 4; im++)
                ldsm4(afr[im][0], afr[im][1], afr[im][2], afr[im][3],
                      stb + a_frag + im * (16 * ROWB) + koff);
#pragma unroll
            for (int im = 0; im < 4; im++) {
#pragma unroll
                for (int p = 0; p < 2; p++) {
                    mma_bf16(acc[im][2 * p],     afr[im][0], afr[im][1], afr[im][2], afr[im][3],
                             bfr[p][0], bfr[p][2]);
                    mma_bf16(acc[im][2 * p + 1], afr[im][0], afr[im][1], afr[im][2], afr[im][3],
                             bfr[p][1], bfr[p][3]);
                }
            }
        }
        __syncthreads();
    }

    const float* bp = bias + cid * D_H + n0;

    if (!POOL) {
#pragma unroll
        for (int im = 0; im < 4; im++) {
            int rg = m0 + wm * 64 + im * 16 + g;
            int rg8 = rg + 8;
#pragma unroll
            for (int in = 0; in < 4; in++) {
                int col = wn * 32 + in * 8 + 2 * tig;
                float b0v = bp[col], b1v = bp[col + 1];
                if (rg < M) {
                    __nv_bfloat162 v = __floats2bfloat162_rn(
                        fmaxf(acc[im][in][0] + b0v, 0.f), fmaxf(acc[im][in][1] + b1v, 0.f));
                    *(__nv_bfloat162*)&g_H1[(size_t)(seg + rg) * D_H + n0 + col] = v;
                }
                if (rg8 < M) {
                    __nv_bfloat162 v = __floats2bfloat162_rn(
                        fmaxf(acc[im][in][2] + b0v, 0.f), fmaxf(acc[im][in][3] + b1v, 0.f));
                    *(__nv_bfloat162*)&g_H1[(size_t)(seg + rg8) * D_H + n0 + col] = v;
                }
            }
        }
    } else {
        if (tid < 128) s_col[tid] = 0.f;
        __syncthreads();
#pragma unroll
        for (int in = 0; in < 4; in++) {
            int col = wn * 32 + in * 8 + 2 * tig;
            float b0v = bp[col], b1v = bp[col + 1];
            float px = 0.f, py = 0.f;
#pragma unroll
            for (int im = 0; im < 4; im++) {
                int rg = m0 + wm * 64 + im * 16 + g;
                if (rg < M) {
                    px += fmaxf(acc[im][in][0] + b0v, 0.f);
                    py += fmaxf(acc[im][in][1] + b1v, 0.f);
                }
                if (rg + 8 < M) {
                    px += fmaxf(acc[im][in][2] + b0v, 0.f);
                    py += fmaxf(acc[im][in][3] + b1v, 0.f);
                }
            }
            atomicAdd(&s_col[col], px);
            atomicAdd(&s_col[col + 1], py);
        }
        __syncthreads();
        if (tid < 128) atomicAdd(&g_pool[cid * D_H + n0 + tid], s_col[tid]);
    }
}

// ---------------- epilogue chain ----------------
__global__ void k_fc(const float* __restrict__ Wfc, const float* __restrict__ bfc) {
    int o = blockIdx.x * blockDim.x + threadIdx.x;
    if (o >= C_CLUST * D_H) return;
    int c = o >> 9;
    int j = o & 511;
    float inv = 1.f / (float)max(g_count[c], 1);
    const float* p = &g_pool[c * D_H];
    float s = 0.f;
#pragma unroll 8
    for (int k = 0; k < D_H; k++) s += p[k] * Wfc[k * D_H + j];
    g_hbuf[o] = fmaxf(s * inv + bfc[j], 0.f);
}

__global__ void k_att(const float* __restrict__ Wa, const float* __restrict__ ba,
                      const float* __restrict__ Wb, const float* __restrict__ bb,
                      const float* __restrict__ Wc_, const float* __restrict__ bc_) {
    int c = blockIdx.x;
    int t = threadIdx.x;
    __shared__ float sh[D_H];
    for (int i = t; i < D_H; i += 256) sh[i] = g_hbuf[c * D_H + i];
    __syncthreads();
    float sa = 0.f, sb = 0.f;
#pragma unroll 4
    for (int k = 0; k < D_H; k++) {
        float hv = sh[k];
        sa += hv * Wa[k * D_ATT + t];
        sb += hv * Wb[k * D_ATT + t];
    }
    float gate = tanhf(sa + ba[t]) * (1.f / (1.f + expf(-(sb + bb[t]))));
    __shared__ float red[256];
    red[t] = gate * Wc_[t];
    __syncthreads();
    for (int s = 128; s > 0; s >>= 1) {
        if (t < s) red[t] += red[t + s];
        __syncthreads();
    }
    if (t == 0) g_Araw[c] = red[0] + bc_[0];
}

__global__ void k_final(const float* __restrict__ Wr, const float* __restrict__ br,
                        const float* __restrict__ Wcls, const float* __restrict__ bcls,
                        float* __restrict__ out, int out_size) {
    __shared__ float A[C_CLUST];
    __shared__ float hp[D_H];
    __shared__ float hr[D_ATT];
    __shared__ float lg[N_CLS];
    int t = threadIdx.x;
    if (t == 0) {
        float m = -1e30f;
        for (int c = 0; c < C_CLUST; c++) m = fmaxf(m, g_Araw[c]);
        float s = 0.f;
        for (int c = 0; c < C_CLUST; c++) { A[c] = expf(g_Araw[c] - m); s += A[c]; }
        float inv = 1.f / s;
        for (int c = 0; c < C_CLUST; c++) A[c] *= inv;
    }
    __syncthreads();
    if (t < D_H) {
        float s = 0.f;
#pragma unroll
        for (int c = 0; c < C_CLUST; c++) s += A[c] * g_hbuf[c * D_H + t];
        hp[t] = s;
    }
    __syncthreads();
    if (t < D_ATT) {
        float s = 0.f;
#pragma unroll 4
        for (int k = 0; k < D_H; k++) s += hp[k] * Wr[k * D_ATT + t];
        hr[t] = fmaxf(s + br[t], 0.f);
    }
    __syncthreads();
    if (t < N_CLS) {
        float s = 0.f;
#pragma unroll 4
        for (int k = 0; k < D_ATT; k++) s += hr[k] * Wcls[k * N_CLS + t];
        lg[t] = s + bcls[t];
    }
    __syncthreads();
    if (t == 0) {
        float m = lg[0];
        int am = 0;
        for (int i = 1; i < N_CLS; i++) if (lg[i] > m) { m = lg[i]; am = i; }
        float e[N_CLS], s = 0.f;
        for (int i = 0; i < N_CLS; i++) { e[i] = expf(lg[i] - m); s += e[i]; }
        float vals[9];
        for (int i = 0; i < N_CLS; i++) vals[i] = lg[i];
        for (int i = 0; i < N_CLS; i++) vals[4 + i] = e[i] / s;
        vals[8] = (float)am;
        for (int i = 0; i < out_size; i++) out[i] = (i < 9) ? vals[i] : 0.f;
    }
}

// ---------------- launch ----------------
extern "C" void kernel_launch(void* const* d_in, const int* in_sizes, int n_in,
                              void* d_out, int out_size) {
    const float* x    = (const float*)d_in[0];
    const void*  cid  = d_in[1];
    const float* W1   = (const float*)d_in[2];
    const float* b1   = (const float*)d_in[3];
    const float* W2   = (const float*)d_in[4];
    const float* b2   = (const float*)d_in[5];
    const float* Wfc  = (const float*)d_in[6];
    const float* bfc  = (const float*)d_in[7];
    const float* Wa   = (const float*)d_in[8];
    const float* ba   = (const float*)d_in[9];
    const float* Wb   = (const float*)d_in[10];
    const float* bb   = (const float*)d_in[11];
    const float* Wc_  = (const float*)d_in[12];
    const float* bc_  = (const float*)d_in[13];
    const float* Wr   = (const float*)d_in[14];
    const float* br   = (const float*)d_in[15];
    const float* Wcls = (const float*)d_in[16];
    const float* bcls = (const float*)d_in[17];

    int n = in_sizes[0] / D_IN;

    static __nv_bfloat16* xg_p = nullptr;
    static __nv_bfloat16* h1_p = nullptr;
    static __nv_bfloat16* w1t_p = nullptr;
    static __nv_bfloat16* w2t_p = nullptr;
    if (!xg_p) {
        cudaGetSymbolAddress((void**)&xg_p, g_Xg);
        cudaGetSymbolAddress((void**)&h1_p, g_H1);
        cudaGetSymbolAddress((void**)&w1t_p, g_W1t);
        cudaGetSymbolAddress((void**)&w2t_p, g_W2t);
        cudaFuncSetAttribute(k_gemm<false>, cudaFuncAttributeMaxDynamicSharedMemorySize, SMEM_SZ);
        cudaFuncSetAttribute(k_gemm<true>, cudaFuncAttributeMaxDynamicSharedMemorySize, SMEM_SZ);
    }

    k_init<<<1, 512>>>(cid);
    k_count<<<(n + 255) / 256, 256>>>(cid, n);
    k_offsets<<<1, 32>>>();
    k_scatter<<<(n + 255) / 256, 256>>>(cid, n);
    k_gather<<<n, 256>>>(x, n);

    dim3 tb(32, 8);
    k_tr<<<dim3(D_H / 32, D_IN / 32, C_CLUST), tb>>>(W1, w1t_p, D_IN, D_H);
    k_tr<<<dim3(D_H / 32, D_H / 32, C_CLUST), tb>>>(W2, w2t_p, D_H, D_H);

    dim3 gg((n + 127) / 128, D_H / 128, C_CLUST);
    k_gemm<false><<<gg, 256, SMEM_SZ>>>(xg_p, w1t_p, b1, D_IN);
    k_gemm<true><<<gg, 256, SMEM_SZ>>>(h1_p, w2t_p, b2, D_H);

    k_fc<<<(C_CLUST * D_H + 127) / 128, 128>>>(Wfc, bfc);
    k_att<<<C_CLUST, 256>>>(Wa, ba, Wb, bb, Wc_, bc_);
    k_final<<<1, 512>>>(Wr, br, Wcls, bcls, (float*)d_out, out_size);
}